// round 5
// baseline (speedup 1.0000x reference)
#include <cuda_runtime.h>
#include <math.h>

#define Bq 2
#define Nn 4096
#define Mm 12288
#define Kk 64
#define Hh 64
#define GKk 8
#define NCc 200
#define SCAP 160

// ---------------- scratch (static device globals; no allocation) ----------------
__device__ float4 g_los4[Bq*Nn];   // x,y,z,feat
__device__ float4 g_pix4[Mm];      // x,y,z,|p|^2
__device__ int    g_nbr[Mm*GKk];
__device__ float  g_h0[Bq*Mm*Hh];
__device__ float  g_h1[Bq*Mm*Hh];
__device__ float  g_part[Bq*96*Hh];

// ---------------- K0: precompute packed unit vectors ----------------
__global__ void k_pre(const float* __restrict__ xxx, const float* __restrict__ ptp) {
    int i = blockIdx.x * blockDim.x + threadIdx.x;
    if (i < Bq * Nn) {
        int b = i / Nn, n = i - b * Nn;
        float th = xxx[b * 3 * Nn + n];
        float ph = xxx[b * 3 * Nn + Nn + n];
        float ft = xxx[b * 3 * Nn + 2 * Nn + n];
        float st, ct, sp, cp;
        sincosf(th, &st, &ct);
        sincosf(ph, &sp, &cp);
        g_los4[i] = make_float4(st * cp, st * sp, ct, ft);
    }
    if (i < Mm) {
        float th = ptp[2 * i], ph = ptp[2 * i + 1];
        float st, ct, sp, cp;
        sincosf(th, &st, &ct);
        sincosf(ph, &sp, &cp);
        float x = st * cp, y = st * sp, z = ct;
        g_pix4[i] = make_float4(x, y, z, x * x + y * y + z * z);
    }
}

// ---------------- K1: kNN graph (top-8 by dot, self excluded) ----------------
struct Top8 { float v[8]; int id[8]; float vmin; };

__device__ __forceinline__ void t8_init(Top8& t) {
#pragma unroll
    for (int i = 0; i < 8; i++) { t.v[i] = -1e30f; t.id[i] = -1; }
    t.vmin = -1e30f;
}

__device__ __forceinline__ void t8_push(Top8& t, float s, int j) {
    if (s > t.vmin) {
        bool done = false;
#pragma unroll
        for (int i = 0; i < 8; i++) {
            if (!done && t.v[i] == t.vmin) { t.v[i] = s; t.id[i] = j; done = true; }
        }
        float m = t.v[0];
#pragma unroll
        for (int i = 1; i < 8; i++) m = fminf(m, t.v[i]);
        t.vmin = m;
    }
}

__device__ __forceinline__ void t8_merge(Top8& t, int lane, int* __restrict__ out) {
    for (int r = 0; r < 8; r++) {
        float lv = t.v[0]; int ls = 0;
#pragma unroll
        for (int i = 1; i < 8; i++) { if (t.v[i] > lv) { lv = t.v[i]; ls = i; } }
        float bv = lv; int bl = lane;
        for (int off = 16; off; off >>= 1) {
            float ov = __shfl_down_sync(0xffffffffu, bv, off);
            int   ol = __shfl_down_sync(0xffffffffu, bl, off);
            if (ov > bv) { bv = ov; bl = ol; }
        }
        bl = __shfl_sync(0xffffffffu, bl, 0);
        int wj = -1;
        if (lane == bl) {
#pragma unroll
            for (int i = 0; i < 8; i++) {
                if (i == ls) { wj = t.id[i]; t.v[i] = -1e30f; }
            }
        }
        wj = __shfl_sync(0xffffffffu, wj, bl);
        if (lane == 0) out[r] = wj;
    }
}

__global__ void k_knn() {
    __shared__ float4 sp[1024];
    int tid = threadIdx.x, lane = tid & 31, w = tid >> 5;
    int i0 = blockIdx.x * 16 + w * 2;
    int i1 = i0 + 1;
    float4 p0 = g_pix4[i0];
    float4 p1 = g_pix4[i1];
    Top8 t0, t1; t8_init(t0); t8_init(t1);
    for (int c0 = 0; c0 < Mm; c0 += 1024) {
        for (int t = tid; t < 1024; t += 256) sp[t] = g_pix4[c0 + t];
        __syncthreads();
        for (int l = lane; l < 1024; l += 32) {
            int j = c0 + l;
            float4 c = sp[l];
            float s0 = 2.f * (p0.x * c.x + p0.y * c.y + p0.z * c.z) - c.w;
            float s1 = 2.f * (p1.x * c.x + p1.y * c.y + p1.z * c.z) - c.w;
            if (j == i0) s0 = -1e30f;
            if (j == i1) s1 = -1e30f;
            t8_push(t0, s0, j);
            t8_push(t1, s1, j);
        }
        __syncthreads();
    }
    t8_merge(t0, lane, &g_nbr[i0 * 8]);
    t8_merge(t1, lane, &g_nbr[i1 * 8]);
}

// ---------------- K2: sparse sampler (threshold select, no histogram) ----------------
__global__ void k_samp(const float* __restrict__ aw1, const float* __restrict__ ab1,
                       const float* __restrict__ aw2, const float* __restrict__ ab2,
                       const float* __restrict__ pw,  const float* __restrict__ pb) {
    __shared__ float4 stile[1024];          // 16KB
    __shared__ float  cv[16][SCAP];         // 10KB
    __shared__ int    cid[16][SCAP];        // 10KB
    __shared__ int    scnt[16];
    __shared__ int    sretry;
    __shared__ float  swv[16][Kk];          // 4KB, rank-ordered values
    __shared__ int    swid[16][Kk];         // 4KB
    __shared__ float  spool[16];
    __shared__ float  sw1x[32], sw1d[32], sb1[32], sw2[32];
    __shared__ float  sab2;

    int tid = threadIdx.x, lane = tid & 31, w = tid >> 5;
    int b  = blockIdx.x / 768;
    int m0 = (blockIdx.x % 768) * 16;
    int pA = 2 * w, pB = 2 * w + 1;
    float4 qa = g_pix4[m0 + pA];
    float4 qb = g_pix4[m0 + pB];
    const float4* los = g_los4 + b * Nn;

    if (tid < 32) {
        sw1x[tid] = aw1[tid];
        sw1d[tid] = aw1[32 + tid];
        sb1[tid]  = ab1[tid];
        sw2[tid]  = aw2[tid];
    }
    if (tid == 0) { sretry = 0; sab2 = ab2[0]; }
    if (lane == 0) { scnt[pA] = 0; scnt[pB] = 0; }
    __syncthreads();

    float thrA = 0.9453125f, thrB = 0.9453125f;   // mean count ~112 of 4096
    bool needA = true, needB = true;

    for (int attempt = 0; attempt < 32; attempt++) {
        for (int c0 = 0; c0 < Nn; c0 += 1024) {
            for (int t = tid; t < 1024; t += 256) stile[t] = los[c0 + t];
            __syncthreads();
            if (needA || needB) {
#pragma unroll 4
                for (int l = lane; l < 1024; l += 32) {
                    float4 cd = stile[l];
                    float va = fminf(1.f, fmaxf(-1.f, fmaf(cd.x, qa.x, fmaf(cd.y, qa.y, cd.z * qa.z))));
                    float vb = fminf(1.f, fmaxf(-1.f, fmaf(cd.x, qb.x, fmaf(cd.y, qb.y, cd.z * qb.z))));
                    bool hA = needA && (va > thrA);
                    bool hB = needB && (vb > thrB);
                    // warp-aggregated push for pixel A
                    unsigned mkA = __ballot_sync(0xffffffffu, hA);
                    if (mkA) {
                        int leader = __ffs(mkA) - 1;
                        int base = 0;
                        if (lane == leader) base = atomicAdd(&scnt[pA], __popc(mkA));
                        base = __shfl_sync(0xffffffffu, base, leader);
                        if (hA) {
                            int pos = base + __popc(mkA & ((1u << lane) - 1u));
                            if (pos < SCAP) { cv[pA][pos] = va; cid[pA][pos] = c0 + l; }
                        }
                    }
                    unsigned mkB = __ballot_sync(0xffffffffu, hB);
                    if (mkB) {
                        int leader = __ffs(mkB) - 1;
                        int base = 0;
                        if (lane == leader) base = atomicAdd(&scnt[pB], __popc(mkB));
                        base = __shfl_sync(0xffffffffu, base, leader);
                        if (hB) {
                            int pos = base + __popc(mkB & ((1u << lane) - 1u));
                            if (pos < SCAP) { cv[pB][pos] = vb; cid[pB][pos] = c0 + l; }
                        }
                    }
                }
            }
            __syncthreads();
        }
        int cA = scnt[pA], cB = scnt[pB];
        bool badA = needA && (cA < Kk || cA > SCAP);
        bool badB = needB && (cB < Kk || cB > SCAP);
        if (tid == 0) sretry = 0;
        __syncthreads();
        if ((badA || badB) && lane == 0) sretry = 1;
        __syncthreads();
        if (!sretry) break;
        if (lane == 0) {
            if (badA) scnt[pA] = 0;
            if (badB) scnt[pB] = 0;
        }
        if (badA) { float mg = 1.f - thrA; thrA = (cA < Kk) ? 1.f - 2.f * mg : 1.f - 0.75f * mg; }
        if (badB) { float mg = 1.f - thrB; thrB = (cB < Kk) ? 1.f - 2.f * mg : 1.f - 0.75f * mg; }
        needA = badA; needB = badB;
        __syncthreads();
    }

    // exact top-64 by rank-count (ties -> lowest index); slot = rank (deterministic)
#pragma unroll
    for (int s = 0; s < 2; s++) {
        int pix = (s == 0) ? pA : pB;
        int cnt = min(scnt[pix], SCAP);
        for (int t = lane; t < cnt; t += 32) {
            float v = cv[pix][t]; int id = cid[pix][t];
            int rank = 0;
            for (int j = 0; j < cnt; j++) {
                float vj = cv[pix][j];
                int idj = cid[pix][j];
                rank += (vj > v) || (vj == v && idj < id);
            }
            if (rank < Kk) { swv[pix][rank] = v; swid[pix][rank] = id; }
        }
    }
    __syncwarp();

    // attention MLP + softmax pool per pixel (warp-local, 2 logits per lane)
#pragma unroll
    for (int s = 0; s < 2; s++) {
        int pix = (s == 0) ? pA : pB;
        float v0 = swv[pix][lane], v1 = swv[pix][lane + 32];
        int   i0 = swid[pix][lane], i1 = swid[pix][lane + 32];
        float x0 = los[i0].w, x1 = los[i1].w;
        float d0 = acosf(v0), d1 = acosf(v1);
        float l0 = sab2, l1 = sab2;
#pragma unroll
        for (int j = 0; j < 32; j++) {
            float h0 = fmaf(x0, sw1x[j], fmaf(d0, sw1d[j], sb1[j]));
            float h1 = fmaf(x1, sw1x[j], fmaf(d1, sw1d[j], sb1[j]));
            l0 = fmaf(fmaxf(h0, 0.f), sw2[j], l0);
            l1 = fmaf(fmaxf(h1, 0.f), sw2[j], l1);
        }
        float mx = fmaxf(l0, l1);
#pragma unroll
        for (int off = 16; off; off >>= 1) mx = fmaxf(mx, __shfl_xor_sync(0xffffffffu, mx, off));
        float e0 = __expf(l0 - mx), e1 = __expf(l1 - mx);
        float sm = e0 + e1;
        float wx = e0 * x0 + e1 * x1;
#pragma unroll
        for (int off = 16; off; off >>= 1) {
            sm += __shfl_xor_sync(0xffffffffu, sm, off);
            wx += __shfl_xor_sync(0xffffffffu, wx, off);
        }
        if (lane == 0) spool[pix] = wx / sm;
    }
    __syncthreads();

    // projection: 16 pixels x 64 features
    for (int i = tid; i < 16 * 64; i += 256) {
        int pix = i >> 6, c = i & 63;
        g_h0[(b * Mm + m0 + pix) * 64 + c] = fmaxf(fmaf(spool[pix], pw[c], pb[c]), 0.f);
    }
}

// ---------------- K3: GNN layer, two K=64 phases, 4x4 reg tiling ----------------
// smem floats: sAT[64][65] @0, sW[64][64] @4160, sbias @8256, snbr(int)[512] @8320
#define GNN_SMEMF 8832
__global__ void k_gnn(const float* __restrict__ relw, const float* __restrict__ relb,
                      const float* __restrict__ rootw, int layer, int dir) {
    extern __shared__ float smbuf[];
    float* sAT   = smbuf;                 // [k][r], stride 65
    float* sW    = smbuf + 4160;          // [k][c], stride 64
    float* sbias = smbuf + 8256;
    int*   snbr  = (int*)(smbuf + 8320);

    const float* hin  = dir ? g_h1 : g_h0;
    float*       hout = dir ? g_h0 : g_h1;

    int tid = threadIdx.x;
    int row0 = blockIdx.x * 64;
    int b = row0 / Mm;
    int m0 = row0 - b * Mm;

    // phase A: W = rel, A = neighbor-sum aggregate
    for (int i = tid; i < 4096; i += 256) sW[i] = relw[layer * 4096 + i];
    if (tid < 64) sbias[tid] = relb[layer * 64 + tid];
    for (int i = tid; i < 512; i += 256) snbr[i] = g_nbr[m0 * 8 + i];
    __syncthreads();
    {
        int c = tid & 63, rq = tid >> 6;
        for (int rr = rq; rr < 64; rr += 4) {
            float a = 0.f;
#pragma unroll
            for (int j = 0; j < 8; j++) a += hin[(b * Mm + snbr[rr * 8 + j]) * 64 + c];
            sAT[c * 65 + rr] = a;
        }
    }
    __syncthreads();

    int tx = tid & 15, ty = tid >> 4;
    int r0 = ty * 4, c0 = tx * 4;
    float acc[4][4];
#pragma unroll
    for (int i = 0; i < 4; i++)
#pragma unroll
        for (int j = 0; j < 4; j++) acc[i][j] = sbias[c0 + j];

#pragma unroll 4
    for (int k = 0; k < 64; k++) {
        float a0 = sAT[k * 65 + r0];
        float a1 = sAT[k * 65 + r0 + 1];
        float a2 = sAT[k * 65 + r0 + 2];
        float a3 = sAT[k * 65 + r0 + 3];
        float4 wv = *(const float4*)&sW[k * 64 + c0];
        acc[0][0] = fmaf(a0, wv.x, acc[0][0]); acc[0][1] = fmaf(a0, wv.y, acc[0][1]);
        acc[0][2] = fmaf(a0, wv.z, acc[0][2]); acc[0][3] = fmaf(a0, wv.w, acc[0][3]);
        acc[1][0] = fmaf(a1, wv.x, acc[1][0]); acc[1][1] = fmaf(a1, wv.y, acc[1][1]);
        acc[1][2] = fmaf(a1, wv.z, acc[1][2]); acc[1][3] = fmaf(a1, wv.w, acc[1][3]);
        acc[2][0] = fmaf(a2, wv.x, acc[2][0]); acc[2][1] = fmaf(a2, wv.y, acc[2][1]);
        acc[2][2] = fmaf(a2, wv.z, acc[2][2]); acc[2][3] = fmaf(a2, wv.w, acc[2][3]);
        acc[3][0] = fmaf(a3, wv.x, acc[3][0]); acc[3][1] = fmaf(a3, wv.y, acc[3][1]);
        acc[3][2] = fmaf(a3, wv.z, acc[3][2]); acc[3][3] = fmaf(a3, wv.w, acc[3][3]);
    }
    __syncthreads();

    // phase B: W = root, A = h tile (transposed)
    for (int i = tid; i < 4096; i += 256) sW[i] = rootw[layer * 4096 + i];
    for (int i = tid; i < 4096; i += 256) {
        int r = i >> 6, k = i & 63;
        sAT[k * 65 + r] = hin[row0 * 64 + i];
    }
    __syncthreads();

#pragma unroll 4
    for (int k = 0; k < 64; k++) {
        float a0 = sAT[k * 65 + r0];
        float a1 = sAT[k * 65 + r0 + 1];
        float a2 = sAT[k * 65 + r0 + 2];
        float a3 = sAT[k * 65 + r0 + 3];
        float4 wv = *(const float4*)&sW[k * 64 + c0];
        acc[0][0] = fmaf(a0, wv.x, acc[0][0]); acc[0][1] = fmaf(a0, wv.y, acc[0][1]);
        acc[0][2] = fmaf(a0, wv.z, acc[0][2]); acc[0][3] = fmaf(a0, wv.w, acc[0][3]);
        acc[1][0] = fmaf(a1, wv.x, acc[1][0]); acc[1][1] = fmaf(a1, wv.y, acc[1][1]);
        acc[1][2] = fmaf(a1, wv.z, acc[1][2]); acc[1][3] = fmaf(a1, wv.w, acc[1][3]);
        acc[2][0] = fmaf(a2, wv.x, acc[2][0]); acc[2][1] = fmaf(a2, wv.y, acc[2][1]);
        acc[2][2] = fmaf(a2, wv.z, acc[2][2]); acc[2][3] = fmaf(a2, wv.w, acc[2][3]);
        acc[3][0] = fmaf(a3, wv.x, acc[3][0]); acc[3][1] = fmaf(a3, wv.y, acc[3][1]);
        acc[3][2] = fmaf(a3, wv.z, acc[3][2]); acc[3][3] = fmaf(a3, wv.w, acc[3][3]);
    }

#pragma unroll
    for (int i = 0; i < 4; i++) {
        float4 o;
        o.x = fmaxf(acc[i][0], 0.f);
        o.y = fmaxf(acc[i][1], 0.f);
        o.z = fmaxf(acc[i][2], 0.f);
        o.w = fmaxf(acc[i][3], 0.f);
        *(float4*)&hout[(row0 + r0 + i) * 64 + c0] = o;
    }
}

// ---------------- K4a: partial mean-pool reduction ----------------
__global__ void k_red() {
    __shared__ float part[128];
    int tid = threadIdx.x;
    int blk = blockIdx.x;
    int b = blk / 96, seg = blk % 96;
    int c = tid & 63, half = tid >> 6;
    float a = 0.f;
    int mbase = seg * 128;
    for (int i = half; i < 128; i += 2)
        a += g_h1[(b * Mm + mbase + i) * 64 + c];
    part[tid] = a;
    __syncthreads();
    if (tid < 64) g_part[(b * 96 + seg) * 64 + c] = part[tid] + part[tid + 64];
}

// ---------------- K4b: final reduce + output MLP ----------------
__global__ void k_out(const float* __restrict__ ow1, const float* __restrict__ ob1,
                      const float* __restrict__ ow2, const float* __restrict__ ob2,
                      float* __restrict__ out) {
    __shared__ float sgf[64], shid[64];
    int tid = threadIdx.x;
    int b = blockIdx.x;
    if (tid < 64) {
        float a = 0.f;
        for (int s = 0; s < 96; s++) a += g_part[(b * 96 + s) * 64 + tid];
        sgf[tid] = a * (1.f / (float)Mm);
    }
    __syncthreads();
    if (tid < 64) {
        float a = ob1[tid];
        for (int k = 0; k < 64; k++) a = fmaf(sgf[k], ow1[k * 64 + tid], a);
        shid[tid] = fmaxf(a, 0.f);
    }
    __syncthreads();
    if (tid < NCc) {
        float a = ob2[tid];
        for (int k = 0; k < 64; k++) a = fmaf(shid[k], ow2[k * NCc + tid], a);
        out[b * NCc + tid] = a;
    }
}

// ---------------- launch ----------------
extern "C" void kernel_launch(void* const* d_in, const int* in_sizes, int n_in,
                              void* d_out, int out_size) {
    const float* xxx  = (const float*)d_in[0];
    const float* ptp  = (const float*)d_in[1];
    const float* aw1  = (const float*)d_in[2];
    const float* ab1  = (const float*)d_in[3];
    const float* aw2  = (const float*)d_in[4];
    const float* ab2  = (const float*)d_in[5];
    const float* pw   = (const float*)d_in[6];
    const float* pb   = (const float*)d_in[7];
    const float* relw = (const float*)d_in[8];
    const float* relb = (const float*)d_in[9];
    const float* rootw= (const float*)d_in[10];
    const float* ow1  = (const float*)d_in[11];
    const float* ob1  = (const float*)d_in[12];
    const float* ow2  = (const float*)d_in[13];
    const float* ob2  = (const float*)d_in[14];
    float* out = (float*)d_out;

    (void)in_sizes; (void)n_in; (void)out_size;

    k_pre<<<48, 256>>>(xxx, ptp);
    k_knn<<<Mm / 16, 256>>>();
    k_samp<<<Bq * 768, 256>>>(aw1, ab1, aw2, ab2, pw, pb);

    const int SM3 = GNN_SMEMF * 4;
    cudaFuncSetAttribute(k_gnn, cudaFuncAttributeMaxDynamicSharedMemorySize, SM3);
    k_gnn<<<384, 256, SM3>>>(relw, relb, rootw, 0, 0); // g_h0 -> g_h1
    k_gnn<<<384, 256, SM3>>>(relw, relb, rootw, 1, 1); // g_h1 -> g_h0
    k_gnn<<<384, 256, SM3>>>(relw, relb, rootw, 2, 0); // g_h0 -> g_h1

    k_red<<<Bq * 96, 128>>>();
    k_out<<<Bq, 256>>>(ow1, ob1, ow2, ob2, out);
}

// round 6
// speedup vs baseline: 2.2262x; 2.2262x over previous
#include <cuda_runtime.h>
#include <math.h>

#define Bq 2
#define Nn 4096
#define Mm 12288
#define Kk 64
#define Hh 64
#define GKk 8
#define NCc 200
#define SCAP 192

// ---------------- scratch (static device globals; no allocation) ----------------
__device__ float4 g_los4[Bq*Nn];   // x,y,z,feat
__device__ float4 g_pix4[Mm];      // x,y,z,|p|^2
__device__ int    g_nbr[Mm*GKk];
__device__ float  g_h0[Bq*Mm*Hh];
__device__ float  g_h1[Bq*Mm*Hh];
__device__ float  g_part[Bq*96*Hh];

// ---------------- K0: precompute packed unit vectors ----------------
__global__ void k_pre(const float* __restrict__ xxx, const float* __restrict__ ptp) {
    int i = blockIdx.x * blockDim.x + threadIdx.x;
    if (i < Bq * Nn) {
        int b = i / Nn, n = i - b * Nn;
        float th = xxx[b * 3 * Nn + n];
        float ph = xxx[b * 3 * Nn + Nn + n];
        float ft = xxx[b * 3 * Nn + 2 * Nn + n];
        float st, ct, sp, cp;
        sincosf(th, &st, &ct);
        sincosf(ph, &sp, &cp);
        g_los4[i] = make_float4(st * cp, st * sp, ct, ft);
    }
    if (i < Mm) {
        float th = ptp[2 * i], ph = ptp[2 * i + 1];
        float st, ct, sp, cp;
        sincosf(th, &st, &ct);
        sincosf(ph, &sp, &cp);
        float x = st * cp, y = st * sp, z = ct;
        g_pix4[i] = make_float4(x, y, z, x * x + y * y + z * z);
    }
}

// ---------------- K1: kNN graph (top-8 by dot, self excluded) ----------------
struct Top8 { float v[8]; int id[8]; float vmin; };

__device__ __forceinline__ void t8_init(Top8& t) {
#pragma unroll
    for (int i = 0; i < 8; i++) { t.v[i] = -1e30f; t.id[i] = -1; }
    t.vmin = -1e30f;
}

__device__ __forceinline__ void t8_push(Top8& t, float s, int j) {
    if (s > t.vmin) {
        bool done = false;
#pragma unroll
        for (int i = 0; i < 8; i++) {
            if (!done && t.v[i] == t.vmin) { t.v[i] = s; t.id[i] = j; done = true; }
        }
        float m = t.v[0];
#pragma unroll
        for (int i = 1; i < 8; i++) m = fminf(m, t.v[i]);
        t.vmin = m;
    }
}

__device__ __forceinline__ void t8_merge(Top8& t, int lane, int* __restrict__ out) {
    for (int r = 0; r < 8; r++) {
        float lv = t.v[0]; int ls = 0;
#pragma unroll
        for (int i = 1; i < 8; i++) { if (t.v[i] > lv) { lv = t.v[i]; ls = i; } }
        float bv = lv; int bl = lane;
        for (int off = 16; off; off >>= 1) {
            float ov = __shfl_down_sync(0xffffffffu, bv, off);
            int   ol = __shfl_down_sync(0xffffffffu, bl, off);
            if (ov > bv) { bv = ov; bl = ol; }
        }
        bl = __shfl_sync(0xffffffffu, bl, 0);
        int wj = -1;
        if (lane == bl) {
#pragma unroll
            for (int i = 0; i < 8; i++) {
                if (i == ls) { wj = t.id[i]; t.v[i] = -1e30f; }
            }
        }
        wj = __shfl_sync(0xffffffffu, wj, bl);
        if (lane == 0) out[r] = wj;
    }
}

__global__ void k_knn() {
    __shared__ float4 sp[1024];
    int tid = threadIdx.x, lane = tid & 31, w = tid >> 5;
    int i0 = blockIdx.x * 16 + w * 2;
    int i1 = i0 + 1;
    float4 p0 = g_pix4[i0];
    float4 p1 = g_pix4[i1];
    Top8 t0, t1; t8_init(t0); t8_init(t1);
    for (int c0 = 0; c0 < Mm; c0 += 1024) {
        for (int t = tid; t < 1024; t += 256) sp[t] = g_pix4[c0 + t];
        __syncthreads();
        for (int l = lane; l < 1024; l += 32) {
            int j = c0 + l;
            float4 c = sp[l];
            float s0 = 2.f * (p0.x * c.x + p0.y * c.y + p0.z * c.z) - c.w;
            float s1 = 2.f * (p1.x * c.x + p1.y * c.y + p1.z * c.z) - c.w;
            if (j == i0) s0 = -1e30f;
            if (j == i1) s1 = -1e30f;
            t8_push(t0, s0, j);
            t8_push(t1, s1, j);
        }
        __syncthreads();
    }
    t8_merge(t0, lane, &g_nbr[i0 * 8]);
    t8_merge(t1, lane, &g_nbr[i1 * 8]);
}

// ---------------- K2: sparse sampler (density-aware threshold select) ----------------
__global__ void k_samp(const float* __restrict__ aw1, const float* __restrict__ ab1,
                       const float* __restrict__ aw2, const float* __restrict__ ab2,
                       const float* __restrict__ pw,  const float* __restrict__ pb) {
    __shared__ float4 stile[512];           // 8KB
    __shared__ float  cv[16][SCAP];         // 12KB
    __shared__ int    cid[16][SCAP];        // 12KB
    __shared__ int    scnt[16];
    __shared__ int    sretry;
    __shared__ float  swv[16][Kk];          // 4KB, rank-ordered values
    __shared__ int    swid[16][Kk];         // 4KB
    __shared__ float  spool[16];
    __shared__ float  sw1x[32], sw1d[32], sb1[32], sw2[32];
    __shared__ float  sab2;

    int tid = threadIdx.x, lane = tid & 31, w = tid >> 5;
    int b  = blockIdx.x / 768;
    int m0 = (blockIdx.x % 768) * 16;
    int pA = 2 * w, pB = 2 * w + 1;
    float4 qa = g_pix4[m0 + pA];
    float4 qb = g_pix4[m0 + pB];
    const float4* los = g_los4 + b * Nn;

    if (tid < 32) {
        sw1x[tid] = aw1[tid];
        sw1d[tid] = aw1[32 + tid];
        sb1[tid]  = ab1[tid];
        sw2[tid]  = aw2[tid];
    }
    if (tid == 0) { sretry = 0; sab2 = ab2[0]; }
    if (lane == 0) { scnt[pA] = 0; scnt[pB] = 0; }
    __syncthreads();

    // density-aware initial radius: rho(theta) ~ 1/sin(theta); target count ~112
    float sA = sqrtf(qa.x * qa.x + qa.y * qa.y);
    float sB = sqrtf(qb.x * qb.x + qb.y * qb.y);
    float rA = fmaxf(0.0859f, 0.4145f * sqrtf(sA));
    float rB = fmaxf(0.0859f, 0.4145f * sqrtf(sB));
    float thrA = cosf(rA), thrB = cosf(rB);
    bool needA = true, needB = true;

    for (int attempt = 0; attempt < 24; attempt++) {
        for (int c0 = 0; c0 < Nn; c0 += 512) {
            for (int t = tid; t < 512; t += 256) stile[t] = los[c0 + t];
            __syncthreads();
            if (needA || needB) {
#pragma unroll 4
                for (int l = lane; l < 512; l += 32) {
                    float4 cd = stile[l];
                    float va = fminf(1.f, fmaxf(-1.f, fmaf(cd.x, qa.x, fmaf(cd.y, qa.y, cd.z * qa.z))));
                    float vb = fminf(1.f, fmaxf(-1.f, fmaf(cd.x, qb.x, fmaf(cd.y, qb.y, cd.z * qb.z))));
                    bool hA = needA && (va > thrA);
                    bool hB = needB && (vb > thrB);
                    unsigned mkA = __ballot_sync(0xffffffffu, hA);
                    if (mkA) {
                        int leader = __ffs(mkA) - 1;
                        int base = 0;
                        if (lane == leader) base = atomicAdd(&scnt[pA], __popc(mkA));
                        base = __shfl_sync(0xffffffffu, base, leader);
                        if (hA) {
                            int pos = base + __popc(mkA & ((1u << lane) - 1u));
                            if (pos < SCAP) { cv[pA][pos] = va; cid[pA][pos] = c0 + l; }
                        }
                    }
                    unsigned mkB = __ballot_sync(0xffffffffu, hB);
                    if (mkB) {
                        int leader = __ffs(mkB) - 1;
                        int base = 0;
                        if (lane == leader) base = atomicAdd(&scnt[pB], __popc(mkB));
                        base = __shfl_sync(0xffffffffu, base, leader);
                        if (hB) {
                            int pos = base + __popc(mkB & ((1u << lane) - 1u));
                            if (pos < SCAP) { cv[pB][pos] = vb; cid[pB][pos] = c0 + l; }
                        }
                    }
                }
            }
            __syncthreads();
        }
        int cA = scnt[pA], cB = scnt[pB];
        bool badA = needA && (cA < Kk || cA > SCAP);
        bool badB = needB && (cB < Kk || cB > SCAP);
        if (tid == 0) sretry = 0;
        __syncthreads();
        if ((badA || badB) && lane == 0) sretry = 1;
        __syncthreads();
        if (!sretry) break;
        if (lane == 0) {
            if (badA) scnt[pA] = 0;
            if (badB) scnt[pB] = 0;
        }
        // exact-count rescale: count ~ r^alpha, alpha in [1,2] -> sqrt step never overshoots
        if (badA) {
            float sc = sqrtf(112.f / fmaxf((float)cA, 8.f));
            rA = fminf(rA * fminf(sc, 4.f), 3.15f);
            thrA = cosf(rA);
        }
        if (badB) {
            float sc = sqrtf(112.f / fmaxf((float)cB, 8.f));
            rB = fminf(rB * fminf(sc, 4.f), 3.15f);
            thrB = cosf(rB);
        }
        needA = badA; needB = badB;
        __syncthreads();
    }

    // exact top-64 by rank-count (ties -> lowest index); slot = rank (deterministic)
#pragma unroll
    for (int s = 0; s < 2; s++) {
        int pix = (s == 0) ? pA : pB;
        int cnt = min(scnt[pix], SCAP);
        for (int t = lane; t < cnt; t += 32) {
            float v = cv[pix][t]; int id = cid[pix][t];
            int rank = 0;
            for (int j = 0; j < cnt; j++) {
                float vj = cv[pix][j];
                int idj = cid[pix][j];
                rank += (vj > v) || (vj == v && idj < id);
            }
            if (rank < Kk) { swv[pix][rank] = v; swid[pix][rank] = id; }
        }
    }
    __syncwarp();

    // attention MLP + softmax pool per pixel (warp-local, 2 logits per lane)
#pragma unroll
    for (int s = 0; s < 2; s++) {
        int pix = (s == 0) ? pA : pB;
        float v0 = swv[pix][lane], v1 = swv[pix][lane + 32];
        int   i0 = swid[pix][lane], i1 = swid[pix][lane + 32];
        float x0 = los[i0].w, x1 = los[i1].w;
        float d0 = acosf(v0), d1 = acosf(v1);
        float l0 = sab2, l1 = sab2;
#pragma unroll
        for (int j = 0; j < 32; j++) {
            float h0 = fmaf(x0, sw1x[j], fmaf(d0, sw1d[j], sb1[j]));
            float h1 = fmaf(x1, sw1x[j], fmaf(d1, sw1d[j], sb1[j]));
            l0 = fmaf(fmaxf(h0, 0.f), sw2[j], l0);
            l1 = fmaf(fmaxf(h1, 0.f), sw2[j], l1);
        }
        float mx = fmaxf(l0, l1);
#pragma unroll
        for (int off = 16; off; off >>= 1) mx = fmaxf(mx, __shfl_xor_sync(0xffffffffu, mx, off));
        float e0 = __expf(l0 - mx), e1 = __expf(l1 - mx);
        float sm = e0 + e1;
        float wx = e0 * x0 + e1 * x1;
#pragma unroll
        for (int off = 16; off; off >>= 1) {
            sm += __shfl_xor_sync(0xffffffffu, sm, off);
            wx += __shfl_xor_sync(0xffffffffu, wx, off);
        }
        if (lane == 0) spool[pix] = wx / sm;
    }
    __syncthreads();

    // projection: 16 pixels x 64 features
    for (int i = tid; i < 16 * 64; i += 256) {
        int pix = i >> 6, c = i & 63;
        g_h0[(b * Mm + m0 + pix) * 64 + c] = fmaxf(fmaf(spool[pix], pw[c], pb[c]), 0.f);
    }
}

// ---------------- K3: GNN layer, two K=64 phases, 4x4 reg tiling ----------------
// smem floats: sAT[64][65] @0, sW[64][64] @4160, sbias @8256, snbr(int)[512] @8320
#define GNN_SMEMF 8832
__global__ void k_gnn(const float* __restrict__ relw, const float* __restrict__ relb,
                      const float* __restrict__ rootw, int layer, int dir) {
    extern __shared__ float smbuf[];
    float* sAT   = smbuf;                 // [k][r], stride 65
    float* sW    = smbuf + 4160;          // [k][c], stride 64
    float* sbias = smbuf + 8256;
    int*   snbr  = (int*)(smbuf + 8320);

    const float* hin  = dir ? g_h1 : g_h0;
    float*       hout = dir ? g_h0 : g_h1;

    int tid = threadIdx.x;
    int row0 = blockIdx.x * 64;
    int b = row0 / Mm;
    int m0 = row0 - b * Mm;

    // phase A: W = rel, A = neighbor-sum aggregate
    for (int i = tid; i < 4096; i += 256) sW[i] = relw[layer * 4096 + i];
    if (tid < 64) sbias[tid] = relb[layer * 64 + tid];
    for (int i = tid; i < 512; i += 256) snbr[i] = g_nbr[m0 * 8 + i];
    __syncthreads();
    {
        int c = tid & 63, rq = tid >> 6;
        for (int rr = rq; rr < 64; rr += 4) {
            float a = 0.f;
#pragma unroll
            for (int j = 0; j < 8; j++) a += hin[(b * Mm + snbr[rr * 8 + j]) * 64 + c];
            sAT[c * 65 + rr] = a;
        }
    }
    __syncthreads();

    int tx = tid & 15, ty = tid >> 4;
    int r0 = ty * 4, c0 = tx * 4;
    float acc[4][4];
#pragma unroll
    for (int i = 0; i < 4; i++)
#pragma unroll
        for (int j = 0; j < 4; j++) acc[i][j] = sbias[c0 + j];

#pragma unroll 4
    for (int k = 0; k < 64; k++) {
        float a0 = sAT[k * 65 + r0];
        float a1 = sAT[k * 65 + r0 + 1];
        float a2 = sAT[k * 65 + r0 + 2];
        float a3 = sAT[k * 65 + r0 + 3];
        float4 wv = *(const float4*)&sW[k * 64 + c0];
        acc[0][0] = fmaf(a0, wv.x, acc[0][0]); acc[0][1] = fmaf(a0, wv.y, acc[0][1]);
        acc[0][2] = fmaf(a0, wv.z, acc[0][2]); acc[0][3] = fmaf(a0, wv.w, acc[0][3]);
        acc[1][0] = fmaf(a1, wv.x, acc[1][0]); acc[1][1] = fmaf(a1, wv.y, acc[1][1]);
        acc[1][2] = fmaf(a1, wv.z, acc[1][2]); acc[1][3] = fmaf(a1, wv.w, acc[1][3]);
        acc[2][0] = fmaf(a2, wv.x, acc[2][0]); acc[2][1] = fmaf(a2, wv.y, acc[2][1]);
        acc[2][2] = fmaf(a2, wv.z, acc[2][2]); acc[2][3] = fmaf(a2, wv.w, acc[2][3]);
        acc[3][0] = fmaf(a3, wv.x, acc[3][0]); acc[3][1] = fmaf(a3, wv.y, acc[3][1]);
        acc[3][2] = fmaf(a3, wv.z, acc[3][2]); acc[3][3] = fmaf(a3, wv.w, acc[3][3]);
    }
    __syncthreads();

    // phase B: W = root, A = h tile (transposed)
    for (int i = tid; i < 4096; i += 256) sW[i] = rootw[layer * 4096 + i];
    for (int i = tid; i < 4096; i += 256) {
        int r = i >> 6, k = i & 63;
        sAT[k * 65 + r] = hin[row0 * 64 + i];
    }
    __syncthreads();

#pragma unroll 4
    for (int k = 0; k < 64; k++) {
        float a0 = sAT[k * 65 + r0];
        float a1 = sAT[k * 65 + r0 + 1];
        float a2 = sAT[k * 65 + r0 + 2];
        float a3 = sAT[k * 65 + r0 + 3];
        float4 wv = *(const float4*)&sW[k * 64 + c0];
        acc[0][0] = fmaf(a0, wv.x, acc[0][0]); acc[0][1] = fmaf(a0, wv.y, acc[0][1]);
        acc[0][2] = fmaf(a0, wv.z, acc[0][2]); acc[0][3] = fmaf(a0, wv.w, acc[0][3]);
        acc[1][0] = fmaf(a1, wv.x, acc[1][0]); acc[1][1] = fmaf(a1, wv.y, acc[1][1]);
        acc[1][2] = fmaf(a1, wv.z, acc[1][2]); acc[1][3] = fmaf(a1, wv.w, acc[1][3]);
        acc[2][0] = fmaf(a2, wv.x, acc[2][0]); acc[2][1] = fmaf(a2, wv.y, acc[2][1]);
        acc[2][2] = fmaf(a2, wv.z, acc[2][2]); acc[2][3] = fmaf(a2, wv.w, acc[2][3]);
        acc[3][0] = fmaf(a3, wv.x, acc[3][0]); acc[3][1] = fmaf(a3, wv.y, acc[3][1]);
        acc[3][2] = fmaf(a3, wv.z, acc[3][2]); acc[3][3] = fmaf(a3, wv.w, acc[3][3]);
    }

#pragma unroll
    for (int i = 0; i < 4; i++) {
        float4 o;
        o.x = fmaxf(acc[i][0], 0.f);
        o.y = fmaxf(acc[i][1], 0.f);
        o.z = fmaxf(acc[i][2], 0.f);
        o.w = fmaxf(acc[i][3], 0.f);
        *(float4*)&hout[(row0 + r0 + i) * 64 + c0] = o;
    }
}

// ---------------- K4a: partial mean-pool reduction ----------------
__global__ void k_red() {
    __shared__ float part[128];
    int tid = threadIdx.x;
    int blk = blockIdx.x;
    int b = blk / 96, seg = blk % 96;
    int c = tid & 63, half = tid >> 6;
    float a = 0.f;
    int mbase = seg * 128;
    for (int i = half; i < 128; i += 2)
        a += g_h1[(b * Mm + mbase + i) * 64 + c];
    part[tid] = a;
    __syncthreads();
    if (tid < 64) g_part[(b * 96 + seg) * 64 + c] = part[tid] + part[tid + 64];
}

// ---------------- K4b: final reduce + output MLP ----------------
__global__ void k_out(const float* __restrict__ ow1, const float* __restrict__ ob1,
                      const float* __restrict__ ow2, const float* __restrict__ ob2,
                      float* __restrict__ out) {
    __shared__ float sgf[64], shid[64];
    int tid = threadIdx.x;
    int b = blockIdx.x;
    if (tid < 64) {
        float a = 0.f;
        for (int s = 0; s < 96; s++) a += g_part[(b * 96 + s) * 64 + tid];
        sgf[tid] = a * (1.f / (float)Mm);
    }
    __syncthreads();
    if (tid < 64) {
        float a = ob1[tid];
        for (int k = 0; k < 64; k++) a = fmaf(sgf[k], ow1[k * 64 + tid], a);
        shid[tid] = fmaxf(a, 0.f);
    }
    __syncthreads();
    if (tid < NCc) {
        float a = ob2[tid];
        for (int k = 0; k < 64; k++) a = fmaf(shid[k], ow2[k * NCc + tid], a);
        out[b * NCc + tid] = a;
    }
}

// ---------------- launch ----------------
extern "C" void kernel_launch(void* const* d_in, const int* in_sizes, int n_in,
                              void* d_out, int out_size) {
    const float* xxx  = (const float*)d_in[0];
    const float* ptp  = (const float*)d_in[1];
    const float* aw1  = (const float*)d_in[2];
    const float* ab1  = (const float*)d_in[3];
    const float* aw2  = (const float*)d_in[4];
    const float* ab2  = (const float*)d_in[5];
    const float* pw   = (const float*)d_in[6];
    const float* pb   = (const float*)d_in[7];
    const float* relw = (const float*)d_in[8];
    const float* relb = (const float*)d_in[9];
    const float* rootw= (const float*)d_in[10];
    const float* ow1  = (const float*)d_in[11];
    const float* ob1  = (const float*)d_in[12];
    const float* ow2  = (const float*)d_in[13];
    const float* ob2  = (const float*)d_in[14];
    float* out = (float*)d_out;

    (void)in_sizes; (void)n_in; (void)out_size;

    k_pre<<<48, 256>>>(xxx, ptp);
    k_knn<<<Mm / 16, 256>>>();
    k_samp<<<Bq * 768, 256>>>(aw1, ab1, aw2, ab2, pw, pb);

    const int SM3 = GNN_SMEMF * 4;
    cudaFuncSetAttribute(k_gnn, cudaFuncAttributeMaxDynamicSharedMemorySize, SM3);
    k_gnn<<<384, 256, SM3>>>(relw, relb, rootw, 0, 0); // g_h0 -> g_h1
    k_gnn<<<384, 256, SM3>>>(relw, relb, rootw, 1, 1); // g_h1 -> g_h0
    k_gnn<<<384, 256, SM3>>>(relw, relb, rootw, 2, 0); // g_h0 -> g_h1

    k_red<<<Bq * 96, 128>>>();
    k_out<<<Bq, 256>>>(ow1, ob1, ow2, ob2, out);
}

// round 7
// speedup vs baseline: 2.5501x; 1.1455x over previous
#include <cuda_runtime.h>
#include <math.h>

#define Bq 2
#define Nn 4096
#define Mm 12288
#define Kk 64
#define Hh 64
#define GKk 8
#define NCc 200
#define SCAP 192

// ---------------- scratch (static device globals; no allocation) ----------------
__device__ float4 g_los4[Bq*Nn];   // x,y,z,feat
__device__ float4 g_pix4[Mm];      // x,y,z,|p|^2
__device__ int    g_nbr[Mm*GKk];
__device__ float  g_h0[Bq*Mm*Hh];
__device__ float  g_h1[Bq*Mm*Hh];
__device__ float  g_part[Bq*96*Hh];

// ---------------- K0: precompute packed unit vectors ----------------
__global__ void k_pre(const float* __restrict__ xxx, const float* __restrict__ ptp) {
    int i = blockIdx.x * blockDim.x + threadIdx.x;
    if (i < Bq * Nn) {
        int b = i / Nn, n = i - b * Nn;
        float th = xxx[b * 3 * Nn + n];
        float ph = xxx[b * 3 * Nn + Nn + n];
        float ft = xxx[b * 3 * Nn + 2 * Nn + n];
        float st, ct, sp, cp;
        sincosf(th, &st, &ct);
        sincosf(ph, &sp, &cp);
        g_los4[i] = make_float4(st * cp, st * sp, ct, ft);
    }
    if (i < Mm) {
        float th = ptp[2 * i], ph = ptp[2 * i + 1];
        float st, ct, sp, cp;
        sincosf(th, &st, &ct);
        sincosf(ph, &sp, &cp);
        float x = st * cp, y = st * sp, z = ct;
        g_pix4[i] = make_float4(x, y, z, x * x + y * y + z * z);
    }
}

// ---------------- K1: kNN graph (top-8 by dot, self excluded) ----------------
struct Top8 { float v[8]; int id[8]; float vmin; };

__device__ __forceinline__ void t8_init(Top8& t) {
#pragma unroll
    for (int i = 0; i < 8; i++) { t.v[i] = -1e30f; t.id[i] = -1; }
    t.vmin = -1e30f;
}

__device__ __forceinline__ void t8_push(Top8& t, float s, int j) {
    if (s > t.vmin) {
        bool done = false;
#pragma unroll
        for (int i = 0; i < 8; i++) {
            if (!done && t.v[i] == t.vmin) { t.v[i] = s; t.id[i] = j; done = true; }
        }
        float m = t.v[0];
#pragma unroll
        for (int i = 1; i < 8; i++) m = fminf(m, t.v[i]);
        t.vmin = m;
    }
}

__device__ __forceinline__ void t8_merge(Top8& t, int lane, int* __restrict__ out) {
    for (int r = 0; r < 8; r++) {
        float lv = t.v[0]; int ls = 0;
#pragma unroll
        for (int i = 1; i < 8; i++) { if (t.v[i] > lv) { lv = t.v[i]; ls = i; } }
        float bv = lv; int bl = lane;
        for (int off = 16; off; off >>= 1) {
            float ov = __shfl_down_sync(0xffffffffu, bv, off);
            int   ol = __shfl_down_sync(0xffffffffu, bl, off);
            if (ov > bv) { bv = ov; bl = ol; }
        }
        bl = __shfl_sync(0xffffffffu, bl, 0);
        int wj = -1;
        if (lane == bl) {
#pragma unroll
            for (int i = 0; i < 8; i++) {
                if (i == ls) { wj = t.id[i]; t.v[i] = -1e30f; }
            }
        }
        wj = __shfl_sync(0xffffffffu, wj, bl);
        if (lane == 0) out[r] = wj;
    }
}

__global__ void k_knn() {
    __shared__ float4 sp[1024];
    int tid = threadIdx.x, lane = tid & 31, w = tid >> 5;
    int i0 = blockIdx.x * 16 + w * 2;
    int i1 = i0 + 1;
    float4 p0 = g_pix4[i0];
    float4 p1 = g_pix4[i1];
    Top8 t0, t1; t8_init(t0); t8_init(t1);
    for (int c0 = 0; c0 < Mm; c0 += 1024) {
        for (int t = tid; t < 1024; t += 256) sp[t] = g_pix4[c0 + t];
        __syncthreads();
        for (int l = lane; l < 1024; l += 32) {
            int j = c0 + l;
            float4 c = sp[l];
            float s0 = 2.f * (p0.x * c.x + p0.y * c.y + p0.z * c.z) - c.w;
            float s1 = 2.f * (p1.x * c.x + p1.y * c.y + p1.z * c.z) - c.w;
            if (j == i0) s0 = -1e30f;
            if (j == i1) s1 = -1e30f;
            t8_push(t0, s0, j);
            t8_push(t1, s1, j);
        }
        __syncthreads();
    }
    t8_merge(t0, lane, &g_nbr[i0 * 8]);
    t8_merge(t1, lane, &g_nbr[i1 * 8]);
}

// ---------------- K2: sparse sampler (count-first, warp-private, atomic-free) ----------------
__device__ __forceinline__ int wred(int v) {
#pragma unroll
    for (int off = 16; off; off >>= 1) v += __shfl_xor_sync(0xffffffffu, v, off);
    return v;
}

__global__ void k_samp(const float* __restrict__ aw1, const float* __restrict__ ab1,
                       const float* __restrict__ aw2, const float* __restrict__ ab2,
                       const float* __restrict__ pw,  const float* __restrict__ pb) {
    __shared__ float  cv[16][SCAP];         // 12KB
    __shared__ int    cid[16][SCAP];        // 12KB
    __shared__ float  swv[16][Kk];          // 4KB
    __shared__ int    swid[16][Kk];         // 4KB
    __shared__ float  spool[16];
    __shared__ float  sw1x[32], sw1d[32], sb1[32], sw2[32];
    __shared__ float  sab2v;

    int tid = threadIdx.x, lane = tid & 31, w = tid >> 5;
    int b  = blockIdx.x / 768;
    int m0 = (blockIdx.x % 768) * 16;
    int pA = 2 * w, pB = 2 * w + 1;
    float4 qa = g_pix4[m0 + pA];
    float4 qb = g_pix4[m0 + pB];
    const float4* __restrict__ los = g_los4 + b * Nn;

    if (tid < 32) {
        sw1x[tid] = aw1[tid];
        sw1d[tid] = aw1[32 + tid];
        sb1[tid]  = ab1[tid];
        sw2[tid]  = aw2[tid];
    }
    if (tid == 0) sab2v = ab2[0];
    __syncthreads();

    // density-aware radius (theta ~ U[0,pi] -> rho ~ 1/sin(theta)); target ~96-112
    float sA = sqrtf(qa.x * qa.x + qa.y * qa.y);
    float sB = sqrtf(qb.x * qb.x + qb.y * qb.y);
    float rA = fmaxf(0.0859f, 0.4145f * sqrtf(sA));
    float rB = fmaxf(0.0859f, 0.4145f * sqrtf(sB));

    float thrA = 0.f, thrB = 0.f;
    int cntA = 0, cntB = 0;
    bool doneA = false, doneB = false;

    for (int att = 0; att < 16 && !(doneA && doneB); att++) {
        float tA0 = cosf(fminf(0.9f * rA, 3.14159f));
        float tA1 = cosf(fminf(rA, 3.14159f));
        float tA2 = cosf(fminf(1.4f * rA, 3.14159f));
        float tB0 = cosf(fminf(0.9f * rB, 3.14159f));
        float tB1 = cosf(fminf(rB, 3.14159f));
        float tB2 = cosf(fminf(1.4f * rB, 3.14159f));
        int a0 = 0, a1 = 0, a2 = 0, b0 = 0, b1 = 0, b2 = 0;
#pragma unroll 4
        for (int n = lane; n < Nn; n += 32) {
            float4 l = los[n];
            float va = fminf(1.f, fmaxf(-1.f, fmaf(l.x, qa.x, fmaf(l.y, qa.y, l.z * qa.z))));
            float vb = fminf(1.f, fmaxf(-1.f, fmaf(l.x, qb.x, fmaf(l.y, qb.y, l.z * qb.z))));
            a0 += (va > tA0); a1 += (va > tA1); a2 += (va > tA2);
            b0 += (vb > tB0); b1 += (vb > tB1); b2 += (vb > tB2);
        }
        a0 = wred(a0); a1 = wred(a1); a2 = wred(a2);
        b0 = wred(b0); b1 = wred(b1); b2 = wred(b2);
        if (!doneA) {
            int c = (a0 >= Kk) ? a0 : ((a1 >= Kk) ? a1 : a2);
            float t = (a0 >= Kk) ? tA0 : ((a1 >= Kk) ? tA1 : tA2);
            if (c >= Kk && c <= SCAP) { thrA = t; cntA = c; doneA = true; }
            else {
                float sc = sqrtf(96.f / fmaxf((float)c, 4.f));
                rA = fminf(rA * fminf(fmaxf(sc, 0.3f), 4.f), 3.14159f);
            }
        }
        if (!doneB) {
            int c = (b0 >= Kk) ? b0 : ((b1 >= Kk) ? b1 : b2);
            float t = (b0 >= Kk) ? tB0 : ((b1 >= Kk) ? tB1 : tB2);
            if (c >= Kk && c <= SCAP) { thrB = t; cntB = c; doneB = true; }
            else {
                float sc = sqrtf(96.f / fmaxf((float)c, 4.f));
                rB = fminf(rB * fminf(fmaxf(sc, 0.3f), 4.f), 3.14159f);
            }
        }
    }

    // collection pass: positions via running base (no atomics)
    {
        int baseA = 0, baseB = 0;
        unsigned ltm = (1u << lane) - 1u;
        for (int n = lane; n < Nn; n += 32) {
            float4 l = los[n];
            float va = fminf(1.f, fmaxf(-1.f, fmaf(l.x, qa.x, fmaf(l.y, qa.y, l.z * qa.z))));
            float vb = fminf(1.f, fmaxf(-1.f, fmaf(l.x, qb.x, fmaf(l.y, qb.y, l.z * qb.z))));
            bool hA = va > thrA;
            bool hB = vb > thrB;
            unsigned mA = __ballot_sync(0xffffffffu, hA);
            unsigned mB = __ballot_sync(0xffffffffu, hB);
            if (hA) {
                int pos = baseA + __popc(mA & ltm);
                if (pos < SCAP) { cv[pA][pos] = va; cid[pA][pos] = n; }
            }
            if (hB) {
                int pos = baseB + __popc(mB & ltm);
                if (pos < SCAP) { cv[pB][pos] = vb; cid[pB][pos] = n; }
            }
            baseA += __popc(mA);
            baseB += __popc(mB);
        }
    }
    __syncwarp();

    // exact top-64 by rank-count (ties -> lowest index); slot = rank (deterministic)
#pragma unroll
    for (int s = 0; s < 2; s++) {
        int pix = (s == 0) ? pA : pB;
        int cnt = min((s == 0) ? cntA : cntB, SCAP);
        for (int t = lane; t < cnt; t += 32) {
            float v = cv[pix][t]; int id = cid[pix][t];
            int rank = 0;
            for (int j = 0; j < cnt; j++) {
                float vj = cv[pix][j];
                int idj = cid[pix][j];
                rank += (vj > v) || (vj == v && idj < id);
            }
            if (rank < Kk) { swv[pix][rank] = v; swid[pix][rank] = id; }
        }
    }
    __syncwarp();

    // attention MLP + softmax pool per pixel (warp-local, 2 logits per lane)
#pragma unroll
    for (int s = 0; s < 2; s++) {
        int pix = (s == 0) ? pA : pB;
        float v0 = swv[pix][lane], v1 = swv[pix][lane + 32];
        int   i0 = swid[pix][lane], i1 = swid[pix][lane + 32];
        float x0 = los[i0].w, x1 = los[i1].w;
        float d0 = acosf(v0), d1 = acosf(v1);
        float l0 = sab2v, l1 = sab2v;
#pragma unroll
        for (int j = 0; j < 32; j++) {
            float h0 = fmaf(x0, sw1x[j], fmaf(d0, sw1d[j], sb1[j]));
            float h1 = fmaf(x1, sw1x[j], fmaf(d1, sw1d[j], sb1[j]));
            l0 = fmaf(fmaxf(h0, 0.f), sw2[j], l0);
            l1 = fmaf(fmaxf(h1, 0.f), sw2[j], l1);
        }
        float mx = fmaxf(l0, l1);
#pragma unroll
        for (int off = 16; off; off >>= 1) mx = fmaxf(mx, __shfl_xor_sync(0xffffffffu, mx, off));
        float e0 = __expf(l0 - mx), e1 = __expf(l1 - mx);
        float sm = e0 + e1;
        float wx = e0 * x0 + e1 * x1;
#pragma unroll
        for (int off = 16; off; off >>= 1) {
            sm += __shfl_xor_sync(0xffffffffu, sm, off);
            wx += __shfl_xor_sync(0xffffffffu, wx, off);
        }
        if (lane == 0) spool[pix] = wx / sm;
    }
    __syncthreads();

    // projection: 16 pixels x 64 features
    for (int i = tid; i < 16 * 64; i += 256) {
        int pix = i >> 6, c = i & 63;
        g_h0[(b * Mm + m0 + pix) * 64 + c] = fmaxf(fmaf(spool[pix], pw[c], pb[c]), 0.f);
    }
}

// ---------------- K3: GNN layer, two K=64 phases, 4x4 reg tiling ----------------
// smem floats: sAT[64][65] @0, sW[64][64] @4160, sbias @8256, snbr(int)[512] @8320
#define GNN_SMEMF 8832
__global__ void k_gnn(const float* __restrict__ relw, const float* __restrict__ relb,
                      const float* __restrict__ rootw, int layer, int dir) {
    extern __shared__ float smbuf[];
    float* sAT   = smbuf;                 // [k][r], stride 65
    float* sW    = smbuf + 4160;          // [k][c], stride 64
    float* sbias = smbuf + 8256;
    int*   snbr  = (int*)(smbuf + 8320);

    const float* hin  = dir ? g_h1 : g_h0;
    float*       hout = dir ? g_h0 : g_h1;

    int tid = threadIdx.x;
    int row0 = blockIdx.x * 64;
    int b = row0 / Mm;
    int m0 = row0 - b * Mm;

    // phase A: W = rel, A = neighbor-sum aggregate
    for (int i = tid; i < 4096; i += 256) sW[i] = relw[layer * 4096 + i];
    if (tid < 64) sbias[tid] = relb[layer * 64 + tid];
    for (int i = tid; i < 512; i += 256) snbr[i] = g_nbr[m0 * 8 + i];
    __syncthreads();
    {
        int c = tid & 63, rq = tid >> 6;
        for (int rr = rq; rr < 64; rr += 4) {
            float a = 0.f;
#pragma unroll
            for (int j = 0; j < 8; j++) a += hin[(b * Mm + snbr[rr * 8 + j]) * 64 + c];
            sAT[c * 65 + rr] = a;
        }
    }
    __syncthreads();

    int tx = tid & 15, ty = tid >> 4;
    int r0 = ty * 4, c0 = tx * 4;
    float acc[4][4];
#pragma unroll
    for (int i = 0; i < 4; i++)
#pragma unroll
        for (int j = 0; j < 4; j++) acc[i][j] = sbias[c0 + j];

#pragma unroll 4
    for (int k = 0; k < 64; k++) {
        float a0 = sAT[k * 65 + r0];
        float a1 = sAT[k * 65 + r0 + 1];
        float a2 = sAT[k * 65 + r0 + 2];
        float a3 = sAT[k * 65 + r0 + 3];
        float4 wv = *(const float4*)&sW[k * 64 + c0];
        acc[0][0] = fmaf(a0, wv.x, acc[0][0]); acc[0][1] = fmaf(a0, wv.y, acc[0][1]);
        acc[0][2] = fmaf(a0, wv.z, acc[0][2]); acc[0][3] = fmaf(a0, wv.w, acc[0][3]);
        acc[1][0] = fmaf(a1, wv.x, acc[1][0]); acc[1][1] = fmaf(a1, wv.y, acc[1][1]);
        acc[1][2] = fmaf(a1, wv.z, acc[1][2]); acc[1][3] = fmaf(a1, wv.w, acc[1][3]);
        acc[2][0] = fmaf(a2, wv.x, acc[2][0]); acc[2][1] = fmaf(a2, wv.y, acc[2][1]);
        acc[2][2] = fmaf(a2, wv.z, acc[2][2]); acc[2][3] = fmaf(a2, wv.w, acc[2][3]);
        acc[3][0] = fmaf(a3, wv.x, acc[3][0]); acc[3][1] = fmaf(a3, wv.y, acc[3][1]);
        acc[3][2] = fmaf(a3, wv.z, acc[3][2]); acc[3][3] = fmaf(a3, wv.w, acc[3][3]);
    }
    __syncthreads();

    // phase B: W = root, A = h tile (transposed)
    for (int i = tid; i < 4096; i += 256) sW[i] = rootw[layer * 4096 + i];
    for (int i = tid; i < 4096; i += 256) {
        int r = i >> 6, k = i & 63;
        sAT[k * 65 + r] = hin[row0 * 64 + i];
    }
    __syncthreads();

#pragma unroll 4
    for (int k = 0; k < 64; k++) {
        float a0 = sAT[k * 65 + r0];
        float a1 = sAT[k * 65 + r0 + 1];
        float a2 = sAT[k * 65 + r0 + 2];
        float a3 = sAT[k * 65 + r0 + 3];
        float4 wv = *(const float4*)&sW[k * 64 + c0];
        acc[0][0] = fmaf(a0, wv.x, acc[0][0]); acc[0][1] = fmaf(a0, wv.y, acc[0][1]);
        acc[0][2] = fmaf(a0, wv.z, acc[0][2]); acc[0][3] = fmaf(a0, wv.w, acc[0][3]);
        acc[1][0] = fmaf(a1, wv.x, acc[1][0]); acc[1][1] = fmaf(a1, wv.y, acc[1][1]);
        acc[1][2] = fmaf(a1, wv.z, acc[1][2]); acc[1][3] = fmaf(a1, wv.w, acc[1][3]);
        acc[2][0] = fmaf(a2, wv.x, acc[2][0]); acc[2][1] = fmaf(a2, wv.y, acc[2][1]);
        acc[2][2] = fmaf(a2, wv.z, acc[2][2]); acc[2][3] = fmaf(a2, wv.w, acc[2][3]);
        acc[3][0] = fmaf(a3, wv.x, acc[3][0]); acc[3][1] = fmaf(a3, wv.y, acc[3][1]);
        acc[3][2] = fmaf(a3, wv.z, acc[3][2]); acc[3][3] = fmaf(a3, wv.w, acc[3][3]);
    }

#pragma unroll
    for (int i = 0; i < 4; i++) {
        float4 o;
        o.x = fmaxf(acc[i][0], 0.f);
        o.y = fmaxf(acc[i][1], 0.f);
        o.z = fmaxf(acc[i][2], 0.f);
        o.w = fmaxf(acc[i][3], 0.f);
        *(float4*)&hout[(row0 + r0 + i) * 64 + c0] = o;
    }
}

// ---------------- K4a: partial mean-pool reduction ----------------
__global__ void k_red() {
    __shared__ float part[128];
    int tid = threadIdx.x;
    int blk = blockIdx.x;
    int b = blk / 96, seg = blk % 96;
    int c = tid & 63, half = tid >> 6;
    float a = 0.f;
    int mbase = seg * 128;
    for (int i = half; i < 128; i += 2)
        a += g_h1[(b * Mm + mbase + i) * 64 + c];
    part[tid] = a;
    __syncthreads();
    if (tid < 64) g_part[(b * 96 + seg) * 64 + c] = part[tid] + part[tid + 64];
}

// ---------------- K4b: final reduce + output MLP ----------------
__global__ void k_out(const float* __restrict__ ow1, const float* __restrict__ ob1,
                      const float* __restrict__ ow2, const float* __restrict__ ob2,
                      float* __restrict__ out) {
    __shared__ float sgf[64], shid[64];
    int tid = threadIdx.x;
    int b = blockIdx.x;
    if (tid < 64) {
        float a = 0.f;
        for (int s = 0; s < 96; s++) a += g_part[(b * 96 + s) * 64 + tid];
        sgf[tid] = a * (1.f / (float)Mm);
    }
    __syncthreads();
    if (tid < 64) {
        float a = ob1[tid];
        for (int k = 0; k < 64; k++) a = fmaf(sgf[k], ow1[k * 64 + tid], a);
        shid[tid] = fmaxf(a, 0.f);
    }
    __syncthreads();
    if (tid < NCc) {
        float a = ob2[tid];
        for (int k = 0; k < 64; k++) a = fmaf(shid[k], ow2[k * NCc + tid], a);
        out[b * NCc + tid] = a;
    }
}

// ---------------- launch ----------------
extern "C" void kernel_launch(void* const* d_in, const int* in_sizes, int n_in,
                              void* d_out, int out_size) {
    const float* xxx  = (const float*)d_in[0];
    const float* ptp  = (const float*)d_in[1];
    const float* aw1  = (const float*)d_in[2];
    const float* ab1  = (const float*)d_in[3];
    const float* aw2  = (const float*)d_in[4];
    const float* ab2  = (const float*)d_in[5];
    const float* pw   = (const float*)d_in[6];
    const float* pb   = (const float*)d_in[7];
    const float* relw = (const float*)d_in[8];
    const float* relb = (const float*)d_in[9];
    const float* rootw= (const float*)d_in[10];
    const float* ow1  = (const float*)d_in[11];
    const float* ob1  = (const float*)d_in[12];
    const float* ow2  = (const float*)d_in[13];
    const float* ob2  = (const float*)d_in[14];
    float* out = (float*)d_out;

    (void)in_sizes; (void)n_in; (void)out_size;

    k_pre<<<48, 256>>>(xxx, ptp);
    k_knn<<<Mm / 16, 256>>>();
    k_samp<<<Bq * 768, 256>>>(aw1, ab1, aw2, ab2, pw, pb);

    const int SM3 = GNN_SMEMF * 4;
    cudaFuncSetAttribute(k_gnn, cudaFuncAttributeMaxDynamicSharedMemorySize, SM3);
    k_gnn<<<384, 256, SM3>>>(relw, relb, rootw, 0, 0); // g_h0 -> g_h1
    k_gnn<<<384, 256, SM3>>>(relw, relb, rootw, 1, 1); // g_h1 -> g_h0
    k_gnn<<<384, 256, SM3>>>(relw, relb, rootw, 2, 0); // g_h0 -> g_h1

    k_red<<<Bq * 96, 128>>>();
    k_out<<<Bq, 256>>>(ow1, ob1, ow2, ob2, out);
}